// round 1
// baseline (speedup 1.0000x reference)
#include <cuda_runtime.h>
#include <math.h>

// ---------------------------------------------------------------------------
// DE3: entropy of a 256-bin histogram over the whole tensor.
//   counts[i] = #{ x in img : floor(x) == i, 0 <= x < 256 }
//   p_i = counts[i] / (H*W);  res = -sum_{p>0} p*log2(p);  out = B*(8 - res)
// Shapes are fixed for this problem: (16, 2048, 2048) fp32 -> temp = 4194304.
// ---------------------------------------------------------------------------

#define NUM_BINS   256
#define HIST_THREADS 128            // 4 warps
#define HIST_BLOCKS  2368           // 16 * 148 SMs -> 303104 threads
// 16777216 float4 / 303104 threads = 56 max iters -> max per-thread count 224 (<255, uint8 safe)

__device__ unsigned int g_counts[NUM_BINS];

__global__ void de3_zero_counts() {
    g_counts[threadIdx.x] = 0u;
}

// Per-thread private uint8 histograms in shared memory, bank-exclusive layout:
//   counter(t, b) byte address = (t>>5)*8192 + (b>>2)*128 + (t&31)*4 + (b&3)
// => the 32-bit word index is (row*32 + lane): every lane only ever touches
//    bank == lane. LDS.U8 / STS.U8 are conflict-free for ANY bin pattern.
__global__ void __launch_bounds__(HIST_THREADS)
de3_hist_kernel(const float4* __restrict__ in4, int n4,
                const float* __restrict__ in, int n) {
    __shared__ unsigned int hist[HIST_THREADS * 64];   // 128 threads * 256 B = 32 KB

    // zero private histograms
    #pragma unroll
    for (int i = threadIdx.x; i < HIST_THREADS * 64; i += HIST_THREADS)
        hist[i] = 0u;
    __syncthreads();

    unsigned char* h8 = reinterpret_cast<unsigned char*>(hist);
    const unsigned lanebase = ((threadIdx.x >> 5) << 13) + ((threadIdx.x & 31) << 2);

    const int stride = gridDim.x * blockDim.x;
    int i = blockIdx.x * blockDim.x + threadIdx.x;

    // main loop: 2x unrolled grid-stride over float4 for load MLP
    for (; i < n4; i += 2 * stride) {
        float4 a = __ldcs(in4 + i);
        bool hb = (i + stride) < n4;
        float4 b4;
        if (hb) b4 = __ldcs(in4 + i + stride);

        #define DE3_BUMP(V) do {                                      \
            unsigned _b = __float2uint_rz(V);                         \
            _b = (_b < 256u) ? _b : 255u;                             \
            unsigned _ofs = ((_b >> 2) << 7) + (_b & 3u);             \
            h8[lanebase + _ofs]++;                                    \
        } while (0)

        DE3_BUMP(a.x); DE3_BUMP(a.y); DE3_BUMP(a.z); DE3_BUMP(a.w);
        if (hb) { DE3_BUMP(b4.x); DE3_BUMP(b4.y); DE3_BUMP(b4.z); DE3_BUMP(b4.w); }
    }

    // scalar tail (n % 4) handled by block 0
    if (blockIdx.x == 0) {
        int rem = n & 3;
        if ((int)threadIdx.x < rem) {
            float v = in[(n & ~3) + threadIdx.x];
            DE3_BUMP(v);
        }
    }
    #undef DE3_BUMP
    __syncthreads();

    // reduction: thread j (<64) owns bins 4j..4j+3 (== word-row j).
    // staggered lane index keeps LDS conflict-free.
    int j = threadIdx.x;
    if (j < 64) {
        unsigned s0 = 0, s1 = 0, s2 = 0, s3 = 0;
        #pragma unroll
        for (int w = 0; w < 4; ++w) {
            #pragma unroll
            for (int k = 0; k < 32; ++k) {
                int l = (k + j) & 31;
                unsigned wd = hist[w * 2048 + j * 32 + l];
                s0 += (wd      ) & 255u;
                s1 += (wd >> 8 ) & 255u;
                s2 += (wd >> 16) & 255u;
                s3 += (wd >> 24);
            }
        }
        atomicAdd(&g_counts[4 * j + 0], s0);
        atomicAdd(&g_counts[4 * j + 1], s1);
        atomicAdd(&g_counts[4 * j + 2], s2);
        atomicAdd(&g_counts[4 * j + 3], s3);
    }
}

__global__ void de3_finalize(float* __restrict__ out, int n) {
    const int t = threadIdx.x;           // 256 threads, one per bin
    const float inv_temp = 1.0f / 4194304.0f;   // 1/(2048*2048)

    unsigned c = g_counts[t];
    float p = (float)c * inv_temp;
    double term = (c > 0u) ? (double)(p * log2f(p)) : 0.0;

    // reduce 256 doubles: warp shuffles + smem
    __shared__ double sred[8];
    double v = term;
    #pragma unroll
    for (int o = 16; o > 0; o >>= 1)
        v += __shfl_down_sync(0xffffffffu, v, o);
    if ((t & 31) == 0) sred[t >> 5] = v;
    __syncthreads();
    if (t == 0) {
        double s = 0.0;
        #pragma unroll
        for (int w = 0; w < 8; ++w) s += sred[w];
        // res = -s;  out = B*(8 - res) = B*(8 + s)
        float B = (float)(n >> 22);      // n / (2048*2048)
        out[0] = (float)((double)B * (8.0 + s));
    }
}

extern "C" void kernel_launch(void* const* d_in, const int* in_sizes, int n_in,
                              void* d_out, int out_size) {
    const float* img = (const float*)d_in[0];
    int n = in_sizes[0];
    float* out = (float*)d_out;

    de3_zero_counts<<<1, NUM_BINS>>>();
    de3_hist_kernel<<<HIST_BLOCKS, HIST_THREADS>>>(
        (const float4*)img, n >> 2, img, n);
    de3_finalize<<<1, NUM_BINS>>>(out, n);
}

// round 2
// speedup vs baseline: 1.0847x; 1.0847x over previous
#include <cuda_runtime.h>
#include <math.h>

// ---------------------------------------------------------------------------
// DE3 fused: 256-bin histogram entropy over whole tensor, single kernel.
//   counts[i] = #{ x : floor(x)==i }, p_i = counts[i]/(H*W),
//   out = B * (8 + sum p_i log2 p_i)     (H*W = 4194304 fixed for this problem)
//
// Per-THREAD private u16 histograms in smem:
//   counter(thread, bin) at byte  warp*16384 + bin*64 + lane*2
//   -> address = IMAD(bin, 64, lanebase): 1 instruction
//   -> lanes 2k/2k+1 share a word (different halves, conflict-free);
//      worst cross-lane conflict is 2-way.
// 6 issue slots per element: FMNMX, F2I, IMAD, LDS.U16, IADD, STS.U16.
//
// Grid = 444 blocks x 128 thr = 56832 threads = 3 blocks/SM (64KB smem each),
// exactly one wave. Max elements/thread = 1185 < 65535: no u16 overflow.
// Last block (ticket) reduces g_counts -> entropy -> out, then resets the
// device globals so every graph replay starts from the same state.
// ---------------------------------------------------------------------------

#define NUM_BINS 256
#define THREADS  128
#define BLOCKS   444
#define SMEM_BYTES 65536   // 4 warps * 256 bins * 64 B

__device__ unsigned int g_counts[NUM_BINS];   // zero-initialized at load
__device__ unsigned int g_done;               // zero-initialized at load

__global__ void __launch_bounds__(THREADS)
de3_fused(const float4* __restrict__ in4, int n4,
          const float* __restrict__ in, int n,
          float* __restrict__ out)
{
    extern __shared__ unsigned char smem[];

    // ---- zero private histograms (4096 uint4 / 128 thr = 32 STS.128) ----
    {
        uint4* z = reinterpret_cast<uint4*>(smem);
        #pragma unroll
        for (int i = threadIdx.x; i < SMEM_BYTES / 16; i += THREADS)
            z[i] = make_uint4(0u, 0u, 0u, 0u);
    }
    __syncthreads();

    const unsigned lane = threadIdx.x & 31u;
    const unsigned warp = threadIdx.x >> 5;
    const unsigned lanebase = (warp << 14) + (lane << 1);  // warp*16KB + lane*2

    // increment: one IMAD for the address, u16 RMW
    #define DE3_BUMP(V) do {                                                  \
        unsigned b_ = __float2uint_rz(fminf((V), 255.0f));                    \
        unsigned short* c_ =                                                  \
            reinterpret_cast<unsigned short*>(smem + (b_ * 64u + lanebase));  \
        *c_ = (unsigned short)(*c_ + 1u);                                     \
    } while (0)

    const int S = gridDim.x * THREADS;
    int i = blockIdx.x * THREADS + threadIdx.x;

    // main loop: 4 float4 loads in flight (16 elements / iter)
    for (; i < n4 - 3 * S; i += 4 * S) {
        float4 a = __ldcs(in4 + i);
        float4 b = __ldcs(in4 + i + S);
        float4 c = __ldcs(in4 + i + 2 * S);
        float4 d = __ldcs(in4 + i + 3 * S);
        DE3_BUMP(a.x); DE3_BUMP(a.y); DE3_BUMP(a.z); DE3_BUMP(a.w);
        DE3_BUMP(b.x); DE3_BUMP(b.y); DE3_BUMP(b.z); DE3_BUMP(b.w);
        DE3_BUMP(c.x); DE3_BUMP(c.y); DE3_BUMP(c.z); DE3_BUMP(c.w);
        DE3_BUMP(d.x); DE3_BUMP(d.y); DE3_BUMP(d.z); DE3_BUMP(d.w);
    }
    for (; i < n4; i += S) {
        float4 a = __ldcs(in4 + i);
        DE3_BUMP(a.x); DE3_BUMP(a.y); DE3_BUMP(a.z); DE3_BUMP(a.w);
    }
    // scalar tail (n % 4), block 0 only (empty for n = 2^26)
    if (blockIdx.x == 0 && (int)threadIdx.x < (n & 3)) {
        float v = in[(n & ~3) + (int)threadIdx.x];
        DE3_BUMP(v);
    }
    #undef DE3_BUMP
    __syncthreads();

    // ---- block reduction: thread j sums bins j and j+128 ------------------
    // Per (warp, bin): 16 words of packed u16 pairs. SIMD-add words (each u16
    // lane <= 1185, 16*1185 < 65536: no carry), unpack once per warp region.
    // Staggered k keeps the 16-thread bank groups conflict-free.
    const unsigned j = threadIdx.x;
    unsigned tot0 = 0u, tot1 = 0u;
    #pragma unroll
    for (int w = 0; w < 4; ++w) {
        const unsigned base0 = ((unsigned)w << 14) + j * 64u;
        const unsigned base1 = ((unsigned)w << 14) + (j + 128u) * 64u;
        unsigned acc0 = 0u, acc1 = 0u;
        #pragma unroll
        for (unsigned s = 0; s < 16; ++s) {
            unsigned k = (((j >> 1) + s) & 15u) << 2;
            acc0 += *reinterpret_cast<const unsigned*>(smem + base0 + k);
            acc1 += *reinterpret_cast<const unsigned*>(smem + base1 + k);
        }
        tot0 += (acc0 & 0xFFFFu) + (acc0 >> 16);
        tot1 += (acc1 & 0xFFFFu) + (acc1 >> 16);
    }
    atomicAdd(&g_counts[j],        tot0);
    atomicAdd(&g_counts[j + 128],  tot1);

    // ---- last-block finalize ----------------------------------------------
    __threadfence();
    __shared__ unsigned ticket;
    if (threadIdx.x == 0) ticket = atomicAdd(&g_done, 1u);
    __syncthreads();

    if (ticket == gridDim.x - 1) {
        const float inv_temp = 1.0f / 4194304.0f;   // 1/(2048*2048)
        unsigned c0 = __ldcg(&g_counts[j]);
        unsigned c1 = __ldcg(&g_counts[j + 128]);
        double term = 0.0;
        if (c0) { float p = (float)c0 * inv_temp; term += (double)(p * log2f(p)); }
        if (c1) { float p = (float)c1 * inv_temp; term += (double)(p * log2f(p)); }

        #pragma unroll
        for (int o = 16; o > 0; o >>= 1)
            term += __shfl_down_sync(0xffffffffu, term, o);

        __shared__ double sred[4];
        if ((threadIdx.x & 31u) == 0u) sred[warp] = term;
        __syncthreads();
        if (threadIdx.x == 0) {
            double s = sred[0] + sred[1] + sred[2] + sred[3];
            float B = (float)(n >> 22);               // n / (2048*2048)
            out[0] = (float)((double)B * (8.0 + s));
        }
        __syncthreads();
        // reset device globals for the next graph replay
        g_counts[j] = 0u;
        g_counts[j + 128] = 0u;
        if (threadIdx.x == 0) g_done = 0u;
    }
}

extern "C" void kernel_launch(void* const* d_in, const int* in_sizes, int n_in,
                              void* d_out, int out_size) {
    const float* img = (const float*)d_in[0];
    int n = in_sizes[0];
    cudaFuncSetAttribute(de3_fused,
                         cudaFuncAttributeMaxDynamicSharedMemorySize, SMEM_BYTES);
    de3_fused<<<BLOCKS, THREADS, SMEM_BYTES>>>(
        (const float4*)img, n >> 2, img, n, (float*)d_out);
}